// round 14
// baseline (speedup 1.0000x reference)
#include <cuda_runtime.h>
#include <math.h>

typedef unsigned long long u64;

#define BATCH 64
#define H 224
#define W 224
#define NPAIR 192            // BATCH*3
#define ACC_STRIDE 132       // 128 hist bins + nc/pc/ma + pad
#define ACC_INTS (5 * NPAIR * ACC_STRIDE)
#define WC (W * 3)           // 672

// patch_rest segments heavy-first: k = 11,9,7,5
#define C11 2
#define C9  3
#define C7  4
#define C5  8
#define O11 0
#define O9  (O11 + C11 * NPAIR)
#define O7  (O9  + C9  * NPAIR)
#define O5  (O7  + C7  * NPAIR)
#define REST_BLOCKS (O5 + C5 * NPAIR)    // 17*192 = 3264
// k=3 kernel: 11 chunks
#define C3  11
#define K3_BLOCKS (C3 * NPAIR)           // 2112

// Device scratch (no allocation allowed)
__device__ float g_planes[3][BATCH * H * W];
__device__ int   g_acc[ACC_INTS];        // zeroed by transpose each launch
__device__ unsigned short g_lut3[512];   // k=3 mask -> {nc | maxarea<<8}
__device__ __align__(16) float g_hrow[BATCH * 5 * WC];   // pre-lerped rows

// Column masks for K=11 (stride 11, 128-bit mask in 2x u64)
constexpr u64 colmask_lo(int c) {
    u64 m = 0;
    for (int r = 0; r < 11; r++) { int p = r * 11 + c; if (p < 64) m |= 1ull << p; }
    return m;
}
constexpr u64 colmask_hi(int c) {
    u64 m = 0;
    for (int r = 0; r < 11; r++) { int p = r * 11 + c; if (p >= 64) m |= 1ull << (p - 64); }
    return m;
}
constexpr u64 NOTC0_LO  = ~colmask_lo(0);
constexpr u64 NOTC0_HI  = ~colmask_hi(0);
constexpr u64 NOTC10_LO = ~colmask_lo(10);
constexpr u64 NOTC10_HI = ~colmask_hi(10);

// ---------------------------------------------------------------------------
// Kernel 1: NHWC -> channel planes (4 triplets/thread) + zero acc + k3 LUT
// ---------------------------------------------------------------------------
__global__ void transpose_kernel(const float4* __restrict__ in4) {
    const int tid = blockIdx.x * blockDim.x + threadIdx.x;
    if (tid < ACC_INTS / 4) ((int4*)g_acc)[tid] = make_int4(0, 0, 0, 0);
    if (tid < 512) {
        int nc = 0, best = 0, rem = tid;
        while (rem) {
            int cur = rem & (-rem);
            while (true) {
                int g = cur | ((cur << 1) & 0x1B6) | ((cur >> 1) & 0x0DB)
                            | (cur << 3) | (cur >> 3);
                g &= rem;
                if (g == cur) break;
                cur = g;
            }
            nc++;
            int a = __popc(cur);
            if (a > best) best = a;
            rem ^= cur;
        }
        g_lut3[tid] = (unsigned short)(nc | (best << 8));
    }

    const int base = blockIdx.x * 1024 + threadIdx.x;
    #pragma unroll
    for (int u = 0; u < 4; u++) {
        const int t = base + u * 256;
        float4 f0 = in4[3 * t + 0];
        float4 f1 = in4[3 * t + 1];
        float4 f2 = in4[3 * t + 2];
        ((float4*)g_planes[0])[t] = make_float4(f0.x, f0.w, f1.z, f2.y);
        ((float4*)g_planes[1])[t] = make_float4(f0.y, f1.x, f1.w, f2.z);
        ((float4*)g_planes[2])[t] = make_float4(f0.z, f1.y, f2.x, f2.w);
    }
}

// 128-bit neighbor expansion (stride 11)
template <int K>
__device__ __forceinline__ void expand128(u64 clo, u64 chi, u64& glo, u64& ghi) {
    u64 l1lo = clo << 1;
    u64 l1hi = (chi << 1) | (clo >> 63);
    u64 r1lo = (clo >> 1) | (chi << 63);
    u64 r1hi = chi >> 1;
    if (K == 11) {
        l1lo &= NOTC0_LO;  l1hi &= NOTC0_HI;
        r1lo &= NOTC10_LO; r1hi &= NOTC10_HI;
    }
    u64 uplo = clo << 11;
    u64 uphi = (chi << 11) | (clo >> 53);
    u64 dnlo = (clo >> 11) | (chi << 53);
    u64 dnhi = chi >> 11;
    glo = l1lo | r1lo | uplo | dnlo;
    ghi = l1hi | r1hi | uphi | dnhi;
}

// ---------------------------------------------------------------------------
// patch_rest body (k=5,7,9,11); singleton + domino elimination, bitmask CC
// ---------------------------------------------------------------------------
template <int K, int CHUNKS, int SEG>
__device__ __forceinline__ void patch_body(int rel, int* sh) {
    constexpr int ROWS = (H + K - 1) / K;
    constexpr int COLS = (W + K - 1) / K;
    constexpr int P    = ROWS * COLS;
    constexpr int PADT = (ROWS * K - H) / 2;
    constexpr int PADL = (COLS * K - W) / 2;
    constexpr int KK   = K * K;
    constexpr int STRIDE = (K <= 7) ? 8 : 11;
    constexpr bool WIDE  = (K > 7);
    constexpr int PTH = (K == 5) ? 15 : (K == 7) ? 30 : (K == 9) ? 49 : 72;

    const int chunk = rel / NPAIR;
    const int pair  = rel % NPAIR;
    const int b  = pair / 3;
    const int ch = pair % 3;
    const float* __restrict__ plane = g_planes[ch] + b * (H * W);

    for (int i = threadIdx.x; i < ACC_STRIDE - 1; i += 256) sh[i] = 0;
    __syncthreads();

    int t_nc = 0, t_pc = 0, t_ma = 0;

    for (int pidx = chunk * 256 + threadIdx.x; pidx < P;
         pidx += CHUNKS * 256) {
        const int i  = pidx / COLS;
        const int j  = pidx % COLS;
        const int r0 = i * K - PADT;
        const int c0 = j * K - PADL;

        const float center = __ldg(plane + (r0 + K / 2) * W + (c0 + K / 2));
        const bool interior = (r0 >= 0) & (c0 >= 0) & (r0 + K <= H) & (c0 + K <= W);

        u64 mlo = 0, mhi = 0;
        if (interior) {
            const float* base = plane + r0 * W + c0;
            #pragma unroll
            for (int dy = 0; dy < K; dy++) {
                unsigned m = 0;
                #pragma unroll
                for (int dx = 0; dx < K; dx++) {
                    float v = __ldg(base + dy * W + dx);
                    if (fabsf(v - center) <= (float)K) m |= (1u << dx);
                }
                int p = dy * STRIDE;
                if (p < 64) {
                    mlo |= (u64)m << p;
                    if (p + K > 64) mhi |= (u64)m >> (64 - p);
                } else {
                    mhi |= (u64)m << (p - 64);
                }
            }
        } else {
            #pragma unroll
            for (int dy = 0; dy < K; dy++) {
                const int r = r0 + dy;
                unsigned m = 0;
                #pragma unroll
                for (int dx = 0; dx < K; dx++) {
                    const int c = c0 + dx;
                    float v = ((unsigned)r < (unsigned)H && (unsigned)c < (unsigned)W)
                                  ? __ldg(plane + r * W + c) : 0.0f;
                    if (fabsf(v - center) <= (float)K) m |= (1u << dx);
                }
                int p = dy * STRIDE;
                if (p < 64) {
                    mlo |= (u64)m << p;
                    if (p + K > 64) mhi |= (u64)m >> (64 - p);
                } else {
                    mhi |= (u64)m << (p - 64);
                }
            }
        }

        int ones, nc, best;

        if (!WIDE) {
            ones = __popcll(mlo);
            best = KK - ones;
            const u64 m = mlo;
            // singleton elimination
            u64 n1 = m << 1, n2 = m >> 1, n3 = m << 8, n4 = m >> 8;
            u64 neigh = n1 | n2 | n3 | n4;
            u64 iso = m & ~neigh;
            nc = __popcll(iso);
            // domino (pair) elimination: deg-1 cells adjacent to deg-1 cells
            u64 s1 = n1 ^ n2, c1 = n1 & n2;
            u64 s2 = n3 ^ n4, c2 = n3 & n4;
            u64 exactly1 = (s1 ^ s2) & ~((s1 & s2) | c1 | c2);
            u64 d1 = m & exactly1;
            u64 dom = d1 & ((d1 << 1) | (d1 >> 1) | (d1 << 8) | (d1 >> 8));
            nc += (int)(__popcll(dom) >> 1);
            u64 rem = m ^ iso ^ dom;
            while (rem) {
                u64 cur = rem & (0ull - rem);
                while (true) {
                    u64 g1 = (cur | (cur << 1) | (cur >> 1) | (cur << 8) | (cur >> 8)) & rem;
                    u64 g2 = (g1 | (g1 << 1) | (g1 >> 1) | (g1 << 8) | (g1 >> 8)) & rem;
                    if (g2 == cur) break;
                    cur = g2;
                }
                int a = __popcll(cur);
                if (a > best) best = a;
                rem ^= cur;
                nc++;
            }
        } else {
            ones = __popcll(mlo) + __popcll(mhi);
            best = KK - ones;
            u64 nlo, nhi;
            expand128<K>(mlo, mhi, nlo, nhi);
            u64 isolo = mlo & ~nlo, isohi = mhi & ~nhi;
            nc = __popcll(isolo) + __popcll(isohi);
            u64 rlo = mlo ^ isolo, rhi = mhi ^ isohi;
            while (rlo | rhi) {
                u64 clo, chi;
                if (rlo) { clo = rlo & (0ull - rlo); chi = 0; }
                else     { clo = 0; chi = rhi & (0ull - rhi); }
                while (true) {
                    u64 elo, ehi, g1lo, g1hi, g2lo, g2hi;
                    expand128<K>(clo, chi, elo, ehi);
                    g1lo = (clo | elo) & rlo;
                    g1hi = (chi | ehi) & rhi;
                    expand128<K>(g1lo, g1hi, elo, ehi);
                    g2lo = (g1lo | elo) & rlo;
                    g2hi = (g1hi | ehi) & rhi;
                    if (g2lo == clo && g2hi == chi) break;
                    clo = g2lo; chi = g2hi;
                }
                int a = __popcll(clo) + __popcll(chi);
                if (a > best) best = a;
                rlo ^= clo; rhi ^= chi;
                nc++;
            }
        }

        // Warp-aggregated histogram add
        {
            unsigned act   = __activemask();
            unsigned peers = __match_any_sync(act, ones);
            int lane = threadIdx.x & 31;
            if (lane == (__ffs(peers) - 1))
                atomicAdd(&sh[ones], __popc(peers));
        }
        t_nc += nc;
        t_pc += (ones >= PTH) ? 1 : 0;
        t_ma += best;
    }

    atomicAdd(&sh[128], t_nc);
    atomicAdd(&sh[129], t_pc);
    atomicAdd(&sh[130], t_ma);
    __syncthreads();

    int* dst = g_acc + (SEG * NPAIR + pair) * ACC_STRIDE;
    for (int i = threadIdx.x; i < ACC_STRIDE - 1; i += 256) {
        int v = sh[i];
        if (v) atomicAdd(&dst[i], v);
    }
}

__global__ __launch_bounds__(256) void patch_rest_kernel() {
    __shared__ int sh[ACC_STRIDE - 1];
    const int blk = blockIdx.x;
    if (blk < O9)       patch_body<11, C11, 0>(blk - O11, sh);
    else if (blk < O7)  patch_body<9,  C9,  1>(blk - O9,  sh);
    else if (blk < O5)  patch_body<7,  C7,  2>(blk - O7,  sh);
    else                patch_body<5,  C5,  3>(blk - O5,  sh);
}

// ---------------------------------------------------------------------------
// patch_k3 kernel: LUT path only (low registers -> high occupancy)
// ---------------------------------------------------------------------------
__global__ __launch_bounds__(256) void patch_k3_kernel() {
    __shared__ int sh[ACC_STRIDE - 1];
    constexpr int COLS = 75, P = 75 * 75;   // 5625
    const int chunk = blockIdx.x / NPAIR;
    const int pair  = blockIdx.x % NPAIR;
    const int b  = pair / 3;
    const int ch = pair % 3;
    const float* __restrict__ plane = g_planes[ch] + b * (H * W);

    for (int q = threadIdx.x; q < ACC_STRIDE - 1; q += 256) sh[q] = 0;
    __syncthreads();

    int t_nc = 0, t_pc = 0, t_ma = 0;

    for (int pidx = chunk * 256 + threadIdx.x; pidx < P; pidx += C3 * 256) {
        const int i  = pidx / COLS;
        const int j  = pidx % COLS;
        const int r0 = i * 3;
        const int c0 = j * 3;

        const float center = __ldg(plane + (r0 + 1) * W + (c0 + 1));
        const bool interior = (r0 + 3 <= H) & (c0 + 3 <= W);

        int m9 = 0;
        if (interior) {
            const float* base = plane + r0 * W + c0;
            #pragma unroll
            for (int dy = 0; dy < 3; dy++)
                #pragma unroll
                for (int dx = 0; dx < 3; dx++) {
                    float v = __ldg(base + dy * W + dx);
                    if (fabsf(v - center) <= 3.0f) m9 |= 1 << (3 * dy + dx);
                }
        } else {
            #pragma unroll
            for (int dy = 0; dy < 3; dy++) {
                const int r = r0 + dy;
                #pragma unroll
                for (int dx = 0; dx < 3; dx++) {
                    const int c = c0 + dx;
                    float v = (r < H && c < W) ? __ldg(plane + r * W + c) : 0.0f;
                    if (fabsf(v - center) <= 3.0f) m9 |= 1 << (3 * dy + dx);
                }
            }
        }

        const int ones = __popc(m9);
        unsigned val = __ldg(&g_lut3[m9]);
        int nc = val & 0xFF;
        int best = val >> 8;
        int bg = 9 - ones;
        if (bg > best) best = bg;

        {
            unsigned act   = __activemask();
            unsigned peers = __match_any_sync(act, ones);
            if ((threadIdx.x & 31) == (__ffs(peers) - 1))
                atomicAdd(&sh[ones], __popc(peers));
        }
        t_nc += nc;
        t_pc += (ones >= 6) ? 1 : 0;
        t_ma += best;
    }

    atomicAdd(&sh[128], t_nc);
    atomicAdd(&sh[129], t_pc);
    atomicAdd(&sh[130], t_ma);
    __syncthreads();

    int* dst = g_acc + (4 * NPAIR + pair) * ACC_STRIDE;
    for (int q = threadIdx.x; q < ACC_STRIDE - 1; q += 256) {
        int v = sh[q];
        if (v) atomicAdd(&dst[q], v);
    }
}

// ---------------------------------------------------------------------------
// Kernel 3: finalize (1 block per image): metrics + pre-lerped rows -> g_hrow
// ---------------------------------------------------------------------------
__global__ __launch_bounds__(256) void finalize_kernel() {
    __shared__ float feat[75];
    const int b   = blockIdx.x;
    const int tid = threadIdx.x;

    if (tid < 15) {
        const int s  = tid / 3;          // g_acc seg (K = 11 - 2s; seg4 = k3)
        const int ch = tid % 3;
        const int K  = (s == 4) ? 3 : 11 - 2 * s;
        const int KK = K * K;
        const int ROWS = (H + K - 1) / K;
        const int COLS = (W + K - 1) / K;
        const int P    = ROWS * COLS;

        const int* acc = g_acc + (s * NPAIR + b * 3 + ch) * ACC_STRIDE;
        const float fP = (float)P;
        float fd = 0.0f, m = 0.0f, m2 = 0.0f;
        for (int q = 0; q < KK; q++) {
            float p = (float)acc[q] / fP;
            float n = (float)(q + 1);
            fd += p / n;
            m  += p * n;
            m2 += p * p * n;
        }
        float lac = (m2 - m * m) / (m * m);
        int acn  = acc[128] / P;
        int acp  = acc[129] / P;
        int acma = acc[130] / P;

        const int kidx = (K - 3) / 2;
        const int o = kidx * 3 + ch;     // feat[(metric*5 + kidx)*3 + ch]
        feat[o + 0 * 15] = (float)acn;
        feat[o + 1 * 15] = (float)acp;
        feat[o + 2 * 15] = (float)acma;
        feat[o + 3 * 15] = lac;
        feat[o + 4 * 15] = fd;
    }
    __syncthreads();

    float* hb = g_hrow + b * (5 * WC);
    for (int i = tid; i < 5 * WC; i += 256) {
        int r  = i / WC;
        int xc = i - r * WC;
        int x  = xc / 3;
        int ch = xc - x * 3;
        float cx = ((float)x + 0.5f) * (5.0f / 224.0f) - 0.5f;
        float fl = floorf(cx);
        int x0 = (int)fl;
        float fx = cx - fl;
        int x0c = max(x0, 0), x1c = min(x0 + 1, 4);
        float a  = feat[(r * 5 + x0c) * 3 + ch];
        float bb = feat[(r * 5 + x1c) * 3 + ch];
        hb[i] = a + fx * (bb - a);
    }
}

// ---------------------------------------------------------------------------
// Kernel 4: resize = pure y-lerp stream from g_hrow
// ---------------------------------------------------------------------------
#define RCH 8
#define YB (H / RCH)          // 28

__global__ __launch_bounds__(256) void resize_kernel(float* __restrict__ out) {
    __shared__ float s_fy[RCH];
    __shared__ int   s_y0[RCH], s_y1[RCH];

    const int b   = blockIdx.x / YB;
    const int yc  = blockIdx.x % YB;
    const int tid = threadIdx.x;

    if (tid < RCH) {
        int y = yc * RCH + tid;
        float cy = ((float)y + 0.5f) * (5.0f / 224.0f) - 0.5f;
        float fl = floorf(cy);
        int y0 = (int)fl;
        float fy = cy - fl;
        int y0c = max(y0, 0), y1c = min(y0 + 1, 4);
        s_fy[tid] = fy;
        s_y0[tid] = y0c * WC;
        s_y1[tid] = y1c * WC;
    }
    __syncthreads();

    const float* hb = g_hrow + b * (5 * WC);
    float4* o4 = (float4*)(out + b * (H * WC) + yc * (RCH * WC));
    const int N4 = RCH * WC / 4;   // 1344
    for (int i = tid; i < N4; i += 256) {
        int yl = i / (WC / 4);
        int x4 = i - yl * (WC / 4);
        const float4 a  = __ldg((const float4*)(hb + s_y0[yl]) + x4);
        const float4 bb = __ldg((const float4*)(hb + s_y1[yl]) + x4);
        const float fy = s_fy[yl];
        float4 v;
        v.x = a.x + fy * (bb.x - a.x);
        v.y = a.y + fy * (bb.y - a.y);
        v.z = a.z + fy * (bb.z - a.z);
        v.w = a.w + fy * (bb.w - a.w);
        o4[i] = v;
    }
}

// ---------------------------------------------------------------------------
extern "C" void kernel_launch(void* const* d_in, const int* in_sizes, int n_in,
                              void* d_out, int out_size) {
    const float4* in4 = (const float4*)d_in[0];
    float* out = (float*)d_out;

    const int NT = BATCH * H * W / 4;   // 802816 = 784 * 1024
    transpose_kernel<<<NT / 1024, 256>>>(in4);
    patch_rest_kernel<<<REST_BLOCKS, 256>>>();
    patch_k3_kernel<<<K3_BLOCKS, 256>>>();
    finalize_kernel<<<BATCH, 256>>>();
    resize_kernel<<<BATCH * YB, 256>>>(out);
}

// round 15
// speedup vs baseline: 1.5864x; 1.5864x over previous
#include <cuda_runtime.h>
#include <math.h>

typedef unsigned long long u64;

#define BATCH 64
#define H 224
#define W 224
#define NPAIR 192            // BATCH*3
#define ACC_STRIDE 132       // 128 hist bins + nc/pc/ma + pad
#define ACC_INTS (5 * NPAIR * ACC_STRIDE)
#define WC (W * 3)           // 672

// Segment order heavy-first: k = 11,9,7,5,3 ; 256-thread blocks (fused)
#define C11 2
#define C9  3
#define C7  4
#define C5  8
#define C3  22
#define O11 0
#define O9  (O11 + C11 * NPAIR)
#define O7  (O9  + C9  * NPAIR)
#define O5  (O7  + C7  * NPAIR)
#define O3  (O5  + C5  * NPAIR)
#define TOTAL_BLOCKS (O3 + C3 * NPAIR)   // 39*192 = 7488

// Device scratch (no allocation allowed)
__device__ float g_planes[3][BATCH * H * W];
__device__ int   g_acc[ACC_INTS];        // zeroed by transpose each launch
__device__ unsigned short g_lut3[512];   // k=3 mask -> {nc | maxarea<<8}
__device__ __align__(16) float g_hrow[BATCH * 5 * WC];   // pre-lerped rows

// Column masks for K=11 (stride 11, 128-bit mask in 2x u64)
constexpr u64 colmask_lo(int c) {
    u64 m = 0;
    for (int r = 0; r < 11; r++) { int p = r * 11 + c; if (p < 64) m |= 1ull << p; }
    return m;
}
constexpr u64 colmask_hi(int c) {
    u64 m = 0;
    for (int r = 0; r < 11; r++) { int p = r * 11 + c; if (p >= 64) m |= 1ull << (p - 64); }
    return m;
}
constexpr u64 NOTC0_LO  = ~colmask_lo(0);
constexpr u64 NOTC0_HI  = ~colmask_hi(0);
constexpr u64 NOTC10_LO = ~colmask_lo(10);
constexpr u64 NOTC10_HI = ~colmask_hi(10);

// ---------------------------------------------------------------------------
// Kernel 1: NHWC -> channel planes (4 triplets/thread) + zero acc + k3 LUT
// ---------------------------------------------------------------------------
__global__ void transpose_kernel(const float4* __restrict__ in4) {
    const int tid = blockIdx.x * blockDim.x + threadIdx.x;
    if (tid < ACC_INTS / 4) ((int4*)g_acc)[tid] = make_int4(0, 0, 0, 0);
    if (tid < 512) {
        int nc = 0, best = 0, rem = tid;
        while (rem) {
            int cur = rem & (-rem);
            while (true) {
                int g = cur | ((cur << 1) & 0x1B6) | ((cur >> 1) & 0x0DB)
                            | (cur << 3) | (cur >> 3);
                g &= rem;
                if (g == cur) break;
                cur = g;
            }
            nc++;
            int a = __popc(cur);
            if (a > best) best = a;
            rem ^= cur;
        }
        g_lut3[tid] = (unsigned short)(nc | (best << 8));
    }

    const int base = blockIdx.x * 1024 + threadIdx.x;
    #pragma unroll
    for (int u = 0; u < 4; u++) {
        const int t = base + u * 256;
        float4 f0 = in4[3 * t + 0];
        float4 f1 = in4[3 * t + 1];
        float4 f2 = in4[3 * t + 2];
        ((float4*)g_planes[0])[t] = make_float4(f0.x, f0.w, f1.z, f2.y);
        ((float4*)g_planes[1])[t] = make_float4(f0.y, f1.x, f1.w, f2.z);
        ((float4*)g_planes[2])[t] = make_float4(f0.z, f1.y, f2.x, f2.w);
    }
}

// 128-bit neighbor expansion (stride 11)
template <int K>
__device__ __forceinline__ void expand128(u64 clo, u64 chi, u64& glo, u64& ghi) {
    u64 l1lo = clo << 1;
    u64 l1hi = (chi << 1) | (clo >> 63);
    u64 r1lo = (clo >> 1) | (chi << 63);
    u64 r1hi = chi >> 1;
    if (K == 11) {
        l1lo &= NOTC0_LO;  l1hi &= NOTC0_HI;
        r1lo &= NOTC10_LO; r1hi &= NOTC10_HI;
    }
    u64 uplo = clo << 11;
    u64 uphi = (chi << 11) | (clo >> 53);
    u64 dnlo = (clo >> 11) | (chi << 53);
    u64 dnhi = chi >> 11;
    glo = l1lo | r1lo | uplo | dnlo;
    ghi = l1hi | r1hi | uphi | dnhi;
}

// ---------------------------------------------------------------------------
// Patch body (templated on K); k=3 via LUT, else singleton-elim bitmask CC
// (R13/R10 measured-best path, double-expand, fused grid)
// ---------------------------------------------------------------------------
template <int K, int CHUNKS, int SEG>
__device__ __forceinline__ void patch_body(int rel, int* sh) {
    constexpr int ROWS = (H + K - 1) / K;
    constexpr int COLS = (W + K - 1) / K;
    constexpr int P    = ROWS * COLS;
    constexpr int PADT = (ROWS * K - H) / 2;
    constexpr int PADL = (COLS * K - W) / 2;
    constexpr int KK   = K * K;
    constexpr int STRIDE = (K <= 7) ? 8 : 11;
    constexpr bool WIDE  = (K > 7);
    constexpr int PTH = (K == 3) ? 6 : (K == 5) ? 15 : (K == 7) ? 30
                       : (K == 9) ? 49 : 72;

    const int chunk = rel / NPAIR;
    const int pair  = rel % NPAIR;
    const int b  = pair / 3;
    const int ch = pair % 3;
    const float* __restrict__ plane = g_planes[ch] + b * (H * W);

    for (int i = threadIdx.x; i < ACC_STRIDE - 1; i += 256) sh[i] = 0;
    __syncthreads();

    int t_nc = 0, t_pc = 0, t_ma = 0;

    for (int pidx = chunk * 256 + threadIdx.x; pidx < P;
         pidx += CHUNKS * 256) {
        const int i  = pidx / COLS;
        const int j  = pidx % COLS;
        const int r0 = i * K - PADT;
        const int c0 = j * K - PADL;

        const float center = __ldg(plane + (r0 + K / 2) * W + (c0 + K / 2));
        const bool interior = (r0 >= 0) & (c0 >= 0) & (r0 + K <= H) & (c0 + K <= W);

        u64 mlo = 0, mhi = 0;
        if (interior) {
            const float* base = plane + r0 * W + c0;
            #pragma unroll
            for (int dy = 0; dy < K; dy++) {
                unsigned m = 0;
                #pragma unroll
                for (int dx = 0; dx < K; dx++) {
                    float v = __ldg(base + dy * W + dx);
                    if (fabsf(v - center) <= (float)K) m |= (1u << dx);
                }
                int p = dy * STRIDE;
                if (p < 64) {
                    mlo |= (u64)m << p;
                    if (p + K > 64) mhi |= (u64)m >> (64 - p);
                } else {
                    mhi |= (u64)m << (p - 64);
                }
            }
        } else {
            #pragma unroll
            for (int dy = 0; dy < K; dy++) {
                const int r = r0 + dy;
                unsigned m = 0;
                #pragma unroll
                for (int dx = 0; dx < K; dx++) {
                    const int c = c0 + dx;
                    float v = ((unsigned)r < (unsigned)H && (unsigned)c < (unsigned)W)
                                  ? __ldg(plane + r * W + c) : 0.0f;
                    if (fabsf(v - center) <= (float)K) m |= (1u << dx);
                }
                int p = dy * STRIDE;
                if (p < 64) {
                    mlo |= (u64)m << p;
                    if (p + K > 64) mhi |= (u64)m >> (64 - p);
                } else {
                    mhi |= (u64)m << (p - 64);
                }
            }
        }

        int ones, nc, best;

        if (K == 3) {
            int m9 = (int)(mlo & 7u) | ((int)(mlo >> 8) & 7) << 3
                   | ((int)(mlo >> 16) & 7) << 6;
            ones = __popc(m9);
            unsigned val = __ldg(&g_lut3[m9]);
            nc = val & 0xFF;
            best = val >> 8;
            int bg = 9 - ones;
            if (bg > best) best = bg;
        } else if (!WIDE) {
            ones = __popcll(mlo);
            best = KK - ones;
            const u64 m = mlo;
            u64 neigh = (m << 1) | (m >> 1) | (m << 8) | (m >> 8);
            u64 iso = m & ~neigh;
            nc = __popcll(iso);
            u64 rem = m ^ iso;
            while (rem) {
                u64 cur = rem & (0ull - rem);
                while (true) {
                    u64 g1 = (cur | (cur << 1) | (cur >> 1) | (cur << 8) | (cur >> 8)) & rem;
                    u64 g2 = (g1 | (g1 << 1) | (g1 >> 1) | (g1 << 8) | (g1 >> 8)) & rem;
                    if (g2 == cur) break;
                    cur = g2;
                }
                int a = __popcll(cur);
                if (a > best) best = a;
                rem ^= cur;
                nc++;
            }
        } else {
            ones = __popcll(mlo) + __popcll(mhi);
            best = KK - ones;
            u64 nlo, nhi;
            expand128<K>(mlo, mhi, nlo, nhi);
            u64 isolo = mlo & ~nlo, isohi = mhi & ~nhi;
            nc = __popcll(isolo) + __popcll(isohi);
            u64 rlo = mlo ^ isolo, rhi = mhi ^ isohi;
            while (rlo | rhi) {
                u64 clo, chi;
                if (rlo) { clo = rlo & (0ull - rlo); chi = 0; }
                else     { clo = 0; chi = rhi & (0ull - rhi); }
                while (true) {
                    u64 elo, ehi, g1lo, g1hi, g2lo, g2hi;
                    expand128<K>(clo, chi, elo, ehi);
                    g1lo = (clo | elo) & rlo;
                    g1hi = (chi | ehi) & rhi;
                    expand128<K>(g1lo, g1hi, elo, ehi);
                    g2lo = (g1lo | elo) & rlo;
                    g2hi = (g1hi | ehi) & rhi;
                    if (g2lo == clo && g2hi == chi) break;
                    clo = g2lo; chi = g2hi;
                }
                int a = __popcll(clo) + __popcll(chi);
                if (a > best) best = a;
                rlo ^= clo; rhi ^= chi;
                nc++;
            }
        }

        // Warp-aggregated histogram add
        {
            unsigned act   = __activemask();
            unsigned peers = __match_any_sync(act, ones);
            int lane = threadIdx.x & 31;
            if (lane == (__ffs(peers) - 1))
                atomicAdd(&sh[ones], __popc(peers));
        }
        t_nc += nc;
        t_pc += (ones >= PTH) ? 1 : 0;
        t_ma += best;
    }

    atomicAdd(&sh[128], t_nc);
    atomicAdd(&sh[129], t_pc);
    atomicAdd(&sh[130], t_ma);
    __syncthreads();

    int* dst = g_acc + (SEG * NPAIR + pair) * ACC_STRIDE;
    for (int i = threadIdx.x; i < ACC_STRIDE - 1; i += 256) {
        int v = sh[i];
        if (v) atomicAdd(&dst[i], v);
    }
}

__global__ __launch_bounds__(256) void patch_all_kernel() {
    __shared__ int sh[ACC_STRIDE - 1];
    const int blk = blockIdx.x;
    if (blk < O9)       patch_body<11, C11, 0>(blk - O11, sh);
    else if (blk < O7)  patch_body<9,  C9,  1>(blk - O9,  sh);
    else if (blk < O5)  patch_body<7,  C7,  2>(blk - O7,  sh);
    else if (blk < O3)  patch_body<5,  C5,  3>(blk - O5,  sh);
    else                patch_body<3,  C3,  4>(blk - O3,  sh);
}

// ---------------------------------------------------------------------------
// Kernel 3: finalize (1 block per image, 512 thr): warp-per-(seg,ch) metric
// reduction (parallel bin loads + shfl reduce), then pre-lerped rows -> g_hrow
// ---------------------------------------------------------------------------
__global__ __launch_bounds__(512) void finalize_kernel() {
    __shared__ float feat[75];
    const int b    = blockIdx.x;
    const int tid  = threadIdx.x;
    const int warp = tid >> 5;
    const int lane = tid & 31;

    if (warp < 15) {
        const int s  = warp / 3;         // g_acc seg (K = 11 - 2s; seg4 = k3)
        const int ch = warp % 3;
        const int K  = 11 - 2 * s;
        const int KK = K * K;
        const int ROWS = (H + K - 1) / K;
        const int COLS = (W + K - 1) / K;
        const int P    = ROWS * COLS;

        const int* acc = g_acc + (s * NPAIR + b * 3 + ch) * ACC_STRIDE;
        const float invP = 1.0f / (float)P;

        float fd = 0.0f, m = 0.0f, m2 = 0.0f;
        for (int q = lane; q < KK; q += 32) {
            float p = (float)__ldg(&acc[q]) * invP;
            float n = (float)(q + 1);
            fd += p / n;
            m  += p * n;
            m2 += p * p * n;
        }
        #pragma unroll
        for (int off = 16; off > 0; off >>= 1) {
            fd += __shfl_xor_sync(0xffffffffu, fd, off);
            m  += __shfl_xor_sync(0xffffffffu, m,  off);
            m2 += __shfl_xor_sync(0xffffffffu, m2, off);
        }

        if (lane == 0) {
            float lac = (m2 - m * m) / (m * m);
            int acn  = __ldg(&acc[128]) / P;
            int acp  = __ldg(&acc[129]) / P;
            int acma = __ldg(&acc[130]) / P;

            const int kidx = 4 - s;
            const int o = kidx * 3 + ch;  // feat[(metric*5 + kidx)*3 + ch]
            feat[o + 0 * 15] = (float)acn;
            feat[o + 1 * 15] = (float)acp;
            feat[o + 2 * 15] = (float)acma;
            feat[o + 3 * 15] = lac;
            feat[o + 4 * 15] = fd;
        }
    }
    __syncthreads();

    float* hb = g_hrow + b * (5 * WC);
    for (int i = tid; i < 5 * WC; i += 512) {
        int r  = i / WC;
        int xc = i - r * WC;
        int x  = xc / 3;
        int ch = xc - x * 3;
        float cx = ((float)x + 0.5f) * (5.0f / 224.0f) - 0.5f;
        float fl = floorf(cx);
        int x0 = (int)fl;
        float fx = cx - fl;
        int x0c = max(x0, 0), x1c = min(x0 + 1, 4);
        float a  = feat[(r * 5 + x0c) * 3 + ch];
        float bb = feat[(r * 5 + x1c) * 3 + ch];
        hb[i] = a + fx * (bb - a);
    }
}

// ---------------------------------------------------------------------------
// Kernel 4: resize = pure y-lerp stream from g_hrow
// ---------------------------------------------------------------------------
#define RCH 8
#define YB (H / RCH)          // 28

__global__ __launch_bounds__(256) void resize_kernel(float* __restrict__ out) {
    __shared__ float s_fy[RCH];
    __shared__ int   s_y0[RCH], s_y1[RCH];

    const int b   = blockIdx.x / YB;
    const int yc  = blockIdx.x % YB;
    const int tid = threadIdx.x;

    if (tid < RCH) {
        int y = yc * RCH + tid;
        float cy = ((float)y + 0.5f) * (5.0f / 224.0f) - 0.5f;
        float fl = floorf(cy);
        int y0 = (int)fl;
        float fy = cy - fl;
        int y0c = max(y0, 0), y1c = min(y0 + 1, 4);
        s_fy[tid] = fy;
        s_y0[tid] = y0c * WC;
        s_y1[tid] = y1c * WC;
    }
    __syncthreads();

    const float* hb = g_hrow + b * (5 * WC);
    float4* o4 = (float4*)(out + b * (H * WC) + yc * (RCH * WC));
    const int N4 = RCH * WC / 4;   // 1344
    for (int i = tid; i < N4; i += 256) {
        int yl = i / (WC / 4);
        int x4 = i - yl * (WC / 4);
        const float4 a  = __ldg((const float4*)(hb + s_y0[yl]) + x4);
        const float4 bb = __ldg((const float4*)(hb + s_y1[yl]) + x4);
        const float fy = s_fy[yl];
        float4 v;
        v.x = a.x + fy * (bb.x - a.x);
        v.y = a.y + fy * (bb.y - a.y);
        v.z = a.z + fy * (bb.z - a.z);
        v.w = a.w + fy * (bb.w - a.w);
        o4[i] = v;
    }
}

// ---------------------------------------------------------------------------
extern "C" void kernel_launch(void* const* d_in, const int* in_sizes, int n_in,
                              void* d_out, int out_size) {
    const float4* in4 = (const float4*)d_in[0];
    float* out = (float*)d_out;

    const int NT = BATCH * H * W / 4;   // 802816 = 784 * 1024
    transpose_kernel<<<NT / 1024, 256>>>(in4);
    patch_all_kernel<<<TOTAL_BLOCKS, 256>>>();
    finalize_kernel<<<BATCH, 512>>>();
    resize_kernel<<<BATCH * YB, 256>>>(out);
}

// round 16
// speedup vs baseline: 1.6772x; 1.0572x over previous
#include <cuda_runtime.h>
#include <math.h>

typedef unsigned long long u64;

#define BATCH 64
#define H 224
#define W 224
#define NPAIR 192            // BATCH*3
#define ACC_STRIDE 132       // 128 hist bins + nc/pc/ma + pad
#define ACC_INTS (5 * NPAIR * ACC_STRIDE)
#define WC (W * 3)           // 672

// Segment order heavy-first: k = 11,9,7,5,3 ; 256-thread blocks (fused)
#define C11 2
#define C9  3
#define C7  4
#define C5  8
#define C3  22
#define O11 0
#define O9  (O11 + C11 * NPAIR)
#define O7  (O9  + C9  * NPAIR)
#define O5  (O7  + C7  * NPAIR)
#define O3  (O5  + C5  * NPAIR)
#define TOTAL_BLOCKS (O3 + C3 * NPAIR)   // 39*192 = 7488

// Device scratch (no allocation allowed)
__device__ float g_planes[3][BATCH * H * W];
__device__ int   g_acc[ACC_INTS];        // zeroed by transpose each launch
__device__ unsigned short g_lut3[512];   // k=3 mask -> {nc | maxarea<<8}
__device__ __align__(16) float g_hrow[BATCH * 5 * WC];   // pre-lerped rows

// Column masks for K=11 (stride 11, 128-bit mask in 2x u64)
constexpr u64 colmask_lo(int c) {
    u64 m = 0;
    for (int r = 0; r < 11; r++) { int p = r * 11 + c; if (p < 64) m |= 1ull << p; }
    return m;
}
constexpr u64 colmask_hi(int c) {
    u64 m = 0;
    for (int r = 0; r < 11; r++) { int p = r * 11 + c; if (p >= 64) m |= 1ull << (p - 64); }
    return m;
}
constexpr u64 NOTC0_LO  = ~colmask_lo(0);
constexpr u64 NOTC0_HI  = ~colmask_hi(0);
constexpr u64 NOTC10_LO = ~colmask_lo(10);
constexpr u64 NOTC10_HI = ~colmask_hi(10);

// ---------------------------------------------------------------------------
// Kernel 1: NHWC -> channel planes (8 triplets/thread) + zero acc + k3 LUT
// ---------------------------------------------------------------------------
__global__ void transpose_kernel(const float4* __restrict__ in4) {
    const int tid = blockIdx.x * blockDim.x + threadIdx.x;
    if (tid < ACC_INTS / 4) ((int4*)g_acc)[tid] = make_int4(0, 0, 0, 0);
    if (tid < 512) {
        int nc = 0, best = 0, rem = tid;
        while (rem) {
            int cur = rem & (-rem);
            while (true) {
                int g = cur | ((cur << 1) & 0x1B6) | ((cur >> 1) & 0x0DB)
                            | (cur << 3) | (cur >> 3);
                g &= rem;
                if (g == cur) break;
                cur = g;
            }
            nc++;
            int a = __popc(cur);
            if (a > best) best = a;
            rem ^= cur;
        }
        g_lut3[tid] = (unsigned short)(nc | (best << 8));
    }

    const int base = blockIdx.x * 2048 + threadIdx.x;
    #pragma unroll
    for (int u = 0; u < 8; u++) {
        const int t = base + u * 256;
        float4 f0 = in4[3 * t + 0];
        float4 f1 = in4[3 * t + 1];
        float4 f2 = in4[3 * t + 2];
        ((float4*)g_planes[0])[t] = make_float4(f0.x, f0.w, f1.z, f2.y);
        ((float4*)g_planes[1])[t] = make_float4(f0.y, f1.x, f1.w, f2.z);
        ((float4*)g_planes[2])[t] = make_float4(f0.z, f1.y, f2.x, f2.w);
    }
}

// 128-bit neighbor expansion (stride 11)
template <int K>
__device__ __forceinline__ void expand128(u64 clo, u64 chi, u64& glo, u64& ghi) {
    u64 l1lo = clo << 1;
    u64 l1hi = (chi << 1) | (clo >> 63);
    u64 r1lo = (clo >> 1) | (chi << 63);
    u64 r1hi = chi >> 1;
    if (K == 11) {
        l1lo &= NOTC0_LO;  l1hi &= NOTC0_HI;
        r1lo &= NOTC10_LO; r1hi &= NOTC10_HI;
    }
    u64 uplo = clo << 11;
    u64 uphi = (chi << 11) | (clo >> 53);
    u64 dnlo = (clo >> 11) | (chi << 53);
    u64 dnhi = chi >> 11;
    glo = l1lo | r1lo | uplo | dnlo;
    ghi = l1hi | r1hi | uphi | dnhi;
}

// ---------------------------------------------------------------------------
// Patch body (templated on K); k=3 via LUT, else singleton-elim bitmask CC
// (measured-best path, unchanged)
// ---------------------------------------------------------------------------
template <int K, int CHUNKS, int SEG>
__device__ __forceinline__ void patch_body(int rel, int* sh) {
    constexpr int ROWS = (H + K - 1) / K;
    constexpr int COLS = (W + K - 1) / K;
    constexpr int P    = ROWS * COLS;
    constexpr int PADT = (ROWS * K - H) / 2;
    constexpr int PADL = (COLS * K - W) / 2;
    constexpr int KK   = K * K;
    constexpr int STRIDE = (K <= 7) ? 8 : 11;
    constexpr bool WIDE  = (K > 7);
    constexpr int PTH = (K == 3) ? 6 : (K == 5) ? 15 : (K == 7) ? 30
                       : (K == 9) ? 49 : 72;

    const int chunk = rel / NPAIR;
    const int pair  = rel % NPAIR;
    const int b  = pair / 3;
    const int ch = pair % 3;
    const float* __restrict__ plane = g_planes[ch] + b * (H * W);

    for (int i = threadIdx.x; i < ACC_STRIDE - 1; i += 256) sh[i] = 0;
    __syncthreads();

    int t_nc = 0, t_pc = 0, t_ma = 0;

    for (int pidx = chunk * 256 + threadIdx.x; pidx < P;
         pidx += CHUNKS * 256) {
        const int i  = pidx / COLS;
        const int j  = pidx % COLS;
        const int r0 = i * K - PADT;
        const int c0 = j * K - PADL;

        const float center = __ldg(plane + (r0 + K / 2) * W + (c0 + K / 2));
        const bool interior = (r0 >= 0) & (c0 >= 0) & (r0 + K <= H) & (c0 + K <= W);

        u64 mlo = 0, mhi = 0;
        if (interior) {
            const float* base = plane + r0 * W + c0;
            #pragma unroll
            for (int dy = 0; dy < K; dy++) {
                unsigned m = 0;
                #pragma unroll
                for (int dx = 0; dx < K; dx++) {
                    float v = __ldg(base + dy * W + dx);
                    if (fabsf(v - center) <= (float)K) m |= (1u << dx);
                }
                int p = dy * STRIDE;
                if (p < 64) {
                    mlo |= (u64)m << p;
                    if (p + K > 64) mhi |= (u64)m >> (64 - p);
                } else {
                    mhi |= (u64)m << (p - 64);
                }
            }
        } else {
            #pragma unroll
            for (int dy = 0; dy < K; dy++) {
                const int r = r0 + dy;
                unsigned m = 0;
                #pragma unroll
                for (int dx = 0; dx < K; dx++) {
                    const int c = c0 + dx;
                    float v = ((unsigned)r < (unsigned)H && (unsigned)c < (unsigned)W)
                                  ? __ldg(plane + r * W + c) : 0.0f;
                    if (fabsf(v - center) <= (float)K) m |= (1u << dx);
                }
                int p = dy * STRIDE;
                if (p < 64) {
                    mlo |= (u64)m << p;
                    if (p + K > 64) mhi |= (u64)m >> (64 - p);
                } else {
                    mhi |= (u64)m << (p - 64);
                }
            }
        }

        int ones, nc, best;

        if (K == 3) {
            int m9 = (int)(mlo & 7u) | ((int)(mlo >> 8) & 7) << 3
                   | ((int)(mlo >> 16) & 7) << 6;
            ones = __popc(m9);
            unsigned val = __ldg(&g_lut3[m9]);
            nc = val & 0xFF;
            best = val >> 8;
            int bg = 9 - ones;
            if (bg > best) best = bg;
        } else if (!WIDE) {
            ones = __popcll(mlo);
            best = KK - ones;
            const u64 m = mlo;
            u64 neigh = (m << 1) | (m >> 1) | (m << 8) | (m >> 8);
            u64 iso = m & ~neigh;
            nc = __popcll(iso);
            u64 rem = m ^ iso;
            while (rem) {
                u64 cur = rem & (0ull - rem);
                while (true) {
                    u64 g1 = (cur | (cur << 1) | (cur >> 1) | (cur << 8) | (cur >> 8)) & rem;
                    u64 g2 = (g1 | (g1 << 1) | (g1 >> 1) | (g1 << 8) | (g1 >> 8)) & rem;
                    if (g2 == cur) break;
                    cur = g2;
                }
                int a = __popcll(cur);
                if (a > best) best = a;
                rem ^= cur;
                nc++;
            }
        } else {
            ones = __popcll(mlo) + __popcll(mhi);
            best = KK - ones;
            u64 nlo, nhi;
            expand128<K>(mlo, mhi, nlo, nhi);
            u64 isolo = mlo & ~nlo, isohi = mhi & ~nhi;
            nc = __popcll(isolo) + __popcll(isohi);
            u64 rlo = mlo ^ isolo, rhi = mhi ^ isohi;
            while (rlo | rhi) {
                u64 clo, chi;
                if (rlo) { clo = rlo & (0ull - rlo); chi = 0; }
                else     { clo = 0; chi = rhi & (0ull - rhi); }
                while (true) {
                    u64 elo, ehi, g1lo, g1hi, g2lo, g2hi;
                    expand128<K>(clo, chi, elo, ehi);
                    g1lo = (clo | elo) & rlo;
                    g1hi = (chi | ehi) & rhi;
                    expand128<K>(g1lo, g1hi, elo, ehi);
                    g2lo = (g1lo | elo) & rlo;
                    g2hi = (g1hi | ehi) & rhi;
                    if (g2lo == clo && g2hi == chi) break;
                    clo = g2lo; chi = g2hi;
                }
                int a = __popcll(clo) + __popcll(chi);
                if (a > best) best = a;
                rlo ^= clo; rhi ^= chi;
                nc++;
            }
        }

        // Warp-aggregated histogram add
        {
            unsigned act   = __activemask();
            unsigned peers = __match_any_sync(act, ones);
            int lane = threadIdx.x & 31;
            if (lane == (__ffs(peers) - 1))
                atomicAdd(&sh[ones], __popc(peers));
        }
        t_nc += nc;
        t_pc += (ones >= PTH) ? 1 : 0;
        t_ma += best;
    }

    atomicAdd(&sh[128], t_nc);
    atomicAdd(&sh[129], t_pc);
    atomicAdd(&sh[130], t_ma);
    __syncthreads();

    int* dst = g_acc + (SEG * NPAIR + pair) * ACC_STRIDE;
    for (int i = threadIdx.x; i < ACC_STRIDE - 1; i += 256) {
        int v = sh[i];
        if (v) atomicAdd(&dst[i], v);
    }
}

__global__ __launch_bounds__(256) void patch_all_kernel() {
    __shared__ int sh[ACC_STRIDE - 1];
    const int blk = blockIdx.x;
    if (blk < O9)       patch_body<11, C11, 0>(blk - O11, sh);
    else if (blk < O7)  patch_body<9,  C9,  1>(blk - O9,  sh);
    else if (blk < O5)  patch_body<7,  C7,  2>(blk - O7,  sh);
    else if (blk < O3)  patch_body<5,  C5,  3>(blk - O5,  sh);
    else                patch_body<3,  C3,  4>(blk - O3,  sh);
}

// ---------------------------------------------------------------------------
// Kernel 3: finalize (1 block per image, 512 thr): warp-per-(seg,ch) metric
// reduction (parallel bin loads + shfl reduce), then pre-lerped rows -> g_hrow
// ---------------------------------------------------------------------------
__global__ __launch_bounds__(512) void finalize_kernel() {
    __shared__ float feat[75];
    const int b    = blockIdx.x;
    const int tid  = threadIdx.x;
    const int warp = tid >> 5;
    const int lane = tid & 31;

    if (warp < 15) {
        const int s  = warp / 3;         // g_acc seg (K = 11 - 2s; seg4 = k3)
        const int ch = warp % 3;
        const int K  = 11 - 2 * s;
        const int KK = K * K;
        const int ROWS = (H + K - 1) / K;
        const int COLS = (W + K - 1) / K;
        const int P    = ROWS * COLS;

        const int* acc = g_acc + (s * NPAIR + b * 3 + ch) * ACC_STRIDE;
        const float invP = 1.0f / (float)P;

        float fd = 0.0f, m = 0.0f, m2 = 0.0f;
        for (int q = lane; q < KK; q += 32) {
            float p = (float)__ldg(&acc[q]) * invP;
            float n = (float)(q + 1);
            fd += p / n;
            m  += p * n;
            m2 += p * p * n;
        }
        #pragma unroll
        for (int off = 16; off > 0; off >>= 1) {
            fd += __shfl_xor_sync(0xffffffffu, fd, off);
            m  += __shfl_xor_sync(0xffffffffu, m,  off);
            m2 += __shfl_xor_sync(0xffffffffu, m2, off);
        }

        if (lane == 0) {
            float lac = (m2 - m * m) / (m * m);
            int acn  = __ldg(&acc[128]) / P;
            int acp  = __ldg(&acc[129]) / P;
            int acma = __ldg(&acc[130]) / P;

            const int kidx = 4 - s;
            const int o = kidx * 3 + ch;  // feat[(metric*5 + kidx)*3 + ch]
            feat[o + 0 * 15] = (float)acn;
            feat[o + 1 * 15] = (float)acp;
            feat[o + 2 * 15] = (float)acma;
            feat[o + 3 * 15] = lac;
            feat[o + 4 * 15] = fd;
        }
    }
    __syncthreads();

    float* hb = g_hrow + b * (5 * WC);
    for (int i = tid; i < 5 * WC; i += 512) {
        int r  = i / WC;
        int xc = i - r * WC;
        int x  = xc / 3;
        int ch = xc - x * 3;
        float cx = ((float)x + 0.5f) * (5.0f / 224.0f) - 0.5f;
        float fl = floorf(cx);
        int x0 = (int)fl;
        float fx = cx - fl;
        int x0c = max(x0, 0), x1c = min(x0 + 1, 4);
        float a  = feat[(r * 5 + x0c) * 3 + ch];
        float bb = feat[(r * 5 + x1c) * 3 + ch];
        hb[i] = a + fx * (bb - a);
    }
}

// ---------------------------------------------------------------------------
// Kernel 4: resize — thread-per-x4-column, y-pair cached across 28-row band
// ---------------------------------------------------------------------------
#define RCH 28
#define YB (H / RCH)          // 8
#define NX4 (WC / 4)          // 168

__global__ __launch_bounds__(192) void resize_kernel(float* __restrict__ out) {
    __shared__ float s_fy[RCH];
    __shared__ int   s_y0[RCH], s_y1[RCH];   // premultiplied by WC

    const int b   = blockIdx.x / YB;
    const int yc  = blockIdx.x % YB;
    const int tid = threadIdx.x;

    if (tid < RCH) {
        int y = yc * RCH + tid;
        float cy = ((float)y + 0.5f) * (5.0f / 224.0f) - 0.5f;
        float fl = floorf(cy);
        int y0 = (int)fl;
        float fy = cy - fl;
        int y0c = max(y0, 0), y1c = min(y0 + 1, 4);
        s_fy[tid] = fy;
        s_y0[tid] = y0c * WC;
        s_y1[tid] = y1c * WC;
    }
    __syncthreads();

    if (tid >= NX4) return;
    const float* hb = g_hrow + b * (5 * WC);
    float4* o4 = (float4*)(out + b * (H * WC) + yc * (RCH * WC));

    int cur0 = -1, cur1 = -1;
    float4 a = make_float4(0.f, 0.f, 0.f, 0.f);
    float4 bb = a;
    #pragma unroll 4
    for (int r = 0; r < RCH; r++) {
        int y0o = s_y0[r], y1o = s_y1[r];
        if (y0o != cur0 || y1o != cur1) {
            cur0 = y0o; cur1 = y1o;
            a  = __ldg((const float4*)(hb + y0o) + tid);
            bb = __ldg((const float4*)(hb + y1o) + tid);
        }
        const float fy = s_fy[r];
        float4 v;
        v.x = a.x + fy * (bb.x - a.x);
        v.y = a.y + fy * (bb.y - a.y);
        v.z = a.z + fy * (bb.z - a.z);
        v.w = a.w + fy * (bb.w - a.w);
        o4[r * NX4 + tid] = v;
    }
}

// ---------------------------------------------------------------------------
extern "C" void kernel_launch(void* const* d_in, const int* in_sizes, int n_in,
                              void* d_out, int out_size) {
    const float4* in4 = (const float4*)d_in[0];
    float* out = (float*)d_out;

    const int NT = BATCH * H * W / 4;   // 802816 = 392 * 2048
    transpose_kernel<<<NT / 2048, 256>>>(in4);
    patch_all_kernel<<<TOTAL_BLOCKS, 256>>>();
    finalize_kernel<<<BATCH, 512>>>();
    resize_kernel<<<BATCH * YB, 192>>>(out);
}